// round 6
// baseline (speedup 1.0000x reference)
#include <cuda_runtime.h>
#include <math.h>

#define BB 4
#define NN 65536
#define CC 192
#define HEADS 6
#define HEADC 32
#define MTOT (BB*NN)
#define TM 128
#define EPS 1e-5f

// only device-global scratch: tiny kv accumulator
__device__ float g_kv[BB * HEADS * HEADC * HEADC];     // kv = (k^T v)/N per (b,h)

__global__ void zero_kv_kernel() {
    int i = blockIdx.x * blockDim.x + threadIdx.x;
    if (i < BB * HEADS * HEADC * HEADC) g_kv[i] = 0.f;
}

// ---------------------------------------------------------------------------
// Kernel 1: k,v projection for one head per block (64 outputs), LN(k), LN(v),
// accumulate kv outer product. (q is computed later in kernel 2.)
// grid: (MTOT/TM, HEADS), block: 256
// dynamic smem: Xs[16][129] + Ws[64][17] + Res[128][65]  = 45,888 B
// ---------------------------------------------------------------------------
__global__ __launch_bounds__(256) void k1_kv(
    const float* __restrict__ x, const float* __restrict__ qkv_w,
    const float* __restrict__ qkv_b,
    const float* __restrict__ klw, const float* __restrict__ klb,
    const float* __restrict__ vlw, const float* __restrict__ vlb)
{
    extern __shared__ float sm[];
    float* Xs  = sm;                       // 16*129 = 2064
    float* Ws  = sm + 16 * 129;            // 64*17  = 1088
    float* Res = sm + 16 * 129 + 64 * 17;  // 128*65 = 8320

    const int tid  = threadIdx.x;
    const int m0   = blockIdx.x * TM;
    const int head = blockIdx.y;
    const int wbase = head * 96 + 32;      // start of k rows; v rows follow

    const int tx = tid & 15;   // cols c = tx + 16*j  (j<4, c<64)
    const int ty = tid >> 4;   // rows r = ty + 16*i  (i<8, r<128)

    float acc[8][4];
    #pragma unroll
    for (int i = 0; i < 8; i++)
        #pragma unroll
        for (int j = 0; j < 4; j++) acc[i][j] = 0.f;

    for (int k0 = 0; k0 < CC; k0 += 16) {
        __syncthreads();
        // X tile: 128 rows x 16 k (transposed into Xs[k][p])
        for (int idx = tid; idx < 512; idx += 256) {
            int p = idx >> 2, kk = (idx & 3) << 2;
            float4 v = *reinterpret_cast<const float4*>(&x[(size_t)(m0 + p) * CC + k0 + kk]);
            Xs[(kk + 0) * 129 + p] = v.x;
            Xs[(kk + 1) * 129 + p] = v.y;
            Xs[(kk + 2) * 129 + p] = v.z;
            Xs[(kk + 3) * 129 + p] = v.w;
        }
        // W tile: 64 rows (k then v) x 16 k  (Ws[d][k])
        for (int idx = tid; idx < 256; idx += 256) {
            int d = idx >> 2, kk = (idx & 3) << 2;
            float4 v = *reinterpret_cast<const float4*>(&qkv_w[(size_t)(wbase + d) * CC + k0 + kk]);
            Ws[d * 17 + kk + 0] = v.x;
            Ws[d * 17 + kk + 1] = v.y;
            Ws[d * 17 + kk + 2] = v.z;
            Ws[d * 17 + kk + 3] = v.w;
        }
        __syncthreads();
        #pragma unroll
        for (int k = 0; k < 16; k++) {
            float a[8], w[4];
            #pragma unroll
            for (int i = 0; i < 8; i++) a[i] = Xs[k * 129 + ty + 16 * i];
            #pragma unroll
            for (int j = 0; j < 4; j++) w[j] = Ws[(tx + 16 * j) * 17 + k];
            #pragma unroll
            for (int i = 0; i < 8; i++)
                #pragma unroll
                for (int j = 0; j < 4; j++) acc[i][j] += a[i] * w[j];
        }
    }
    __syncthreads();

    // results (+bias) into Res[p][c]; c<32 = k, c>=32 = v
    #pragma unroll
    for (int j = 0; j < 4; j++) {
        int c = tx + 16 * j;
        float bv = __ldg(&qkv_b[wbase + c]);
        #pragma unroll
        for (int i = 0; i < 8; i++)
            Res[(ty + 16 * i) * 65 + c] = acc[i][j] + bv;
    }
    __syncthreads();

    // LN on k (cols 0..31) and v (cols 32..63); ddof=1, denom = std + eps
    {
        int p = tid & 127;
        int which = tid >> 7;               // 0 -> k, 1 -> v
        int base = which ? 32 : 0;
        const float* lw = which ? vlw : klw;
        const float* lb = which ? vlb : klb;
        float s = 0.f, s2 = 0.f;
        #pragma unroll
        for (int c = 0; c < 32; c++) {
            float v = Res[p * 65 + base + c];
            s += v; s2 += v * v;
        }
        float mean = s * (1.f / 32.f);
        float var = (s2 - s * mean) * (1.f / 31.f);
        var = fmaxf(var, 0.f);
        float inv = 1.f / (sqrtf(var) + EPS);
        #pragma unroll
        for (int c = 0; c < 32; c++) {
            float v = Res[p * 65 + base + c];
            Res[p * 65 + base + c] =
                __ldg(&lw[head * 32 + c]) * ((v - mean) * inv) + __ldg(&lb[head * 32 + c]);
        }
    }
    __syncthreads();

    // kv outer product: kv[d][e] += sum_p kn[p][d]*vn[p][e], scaled by 1/N
    {
        int d  = tid >> 3;
        int e0 = (tid & 7) << 2;
        float a0 = 0.f, a1 = 0.f, a2 = 0.f, a3 = 0.f;
        for (int p = 0; p < TM; p++) {
            float kd = Res[p * 65 + d];
            a0 += kd * Res[p * 65 + 32 + e0 + 0];
            a1 += kd * Res[p * 65 + 32 + e0 + 1];
            a2 += kd * Res[p * 65 + 32 + e0 + 2];
            a3 += kd * Res[p * 65 + 32 + e0 + 3];
        }
        int bi = m0 / NN;
        float* dst = &g_kv[(((size_t)bi * HEADS + head) * HEADC + d) * HEADC + e0];
        const float sc = 1.f / (float)NN;
        atomicAdd(dst + 0, a0 * sc);
        atomicAdd(dst + 1, a1 * sc);
        atomicAdd(dst + 2, a2 * sc);
        atomicAdd(dst + 3, a3 * sc);
    }
}

// ---------------------------------------------------------------------------
// Kernel 2: q = x@Wq^T + bq ; attn = q@kv ; ret = attn + x ;
//           h = gelu(ret@o1^T + b1) ; out = h@o2^T + b2 + x
// grid: MTOT/TM, block: 256
// dynamic smem: A[128][196] + Bs[128][196] + Ws[6144]  = 225,280 B
// ---------------------------------------------------------------------------
#define ASTR 196

__global__ __launch_bounds__(256) void k2_attn_mlp(
    const float* __restrict__ x,
    const float* __restrict__ qkv_w, const float* __restrict__ qkv_b,
    const float* __restrict__ o1w, const float* __restrict__ o1b,
    const float* __restrict__ o2w, const float* __restrict__ o2b,
    float* __restrict__ out)
{
    extern __shared__ float sm[];
    float* A  = sm;                   // x / ret tile   128*196
    float* Bs = sm + 128 * ASTR;      // q tile / h tile
    float* Ws = sm + 2 * 128 * ASTR;  // weight chunks (192*17=3264) / kv (6144)

    const int tid = threadIdx.x;
    const int m0  = blockIdx.x * TM;
    const int bi  = m0 / NN;

    // stage 0: x -> A
    for (int idx = tid; idx < TM * CC / 4; idx += 256) {
        int p = idx / 48, c4 = (idx % 48) * 4;
        float4 xv = *reinterpret_cast<const float4*>(&x[(size_t)(m0 + p) * CC + c4]);
        *reinterpret_cast<float4*>(&A[p * ASTR + c4]) = xv;
    }
    __syncthreads();

    const int tx = tid & 15;   // cols d = tx + 16*j (j<12)
    const int ty = tid >> 4;   // rows r = ty + 16*i (i<8)

    // ---- q projection: Bs[p][h*32+d] = sum_c A[p][c] * qkv_w[h*96+d][c] + b
    {
        float acc[8][12];
        #pragma unroll
        for (int i = 0; i < 8; i++)
            #pragma unroll
            for (int j = 0; j < 12; j++) acc[i][j] = 0.f;

        for (int k0 = 0; k0 < CC; k0 += 16) {
            __syncthreads();
            for (int idx = tid; idx < 192 * 4; idx += 256) {
                int dd = idx >> 2, kk = (idx & 3) << 2;
                int grow = (dd >> 5) * 96 + (dd & 31);   // q rows of head dd>>5
                float4 v = *reinterpret_cast<const float4*>(&qkv_w[(size_t)grow * CC + k0 + kk]);
                Ws[dd * 17 + kk + 0] = v.x;
                Ws[dd * 17 + kk + 1] = v.y;
                Ws[dd * 17 + kk + 2] = v.z;
                Ws[dd * 17 + kk + 3] = v.w;
            }
            __syncthreads();
            #pragma unroll
            for (int k = 0; k < 16; k++) {
                float a[8], w[12];
                #pragma unroll
                for (int i = 0; i < 8; i++) a[i] = A[(ty + 16 * i) * ASTR + k0 + k];
                #pragma unroll
                for (int j = 0; j < 12; j++) w[j] = Ws[(tx + 16 * j) * 17 + k];
                #pragma unroll
                for (int i = 0; i < 8; i++)
                    #pragma unroll
                    for (int j = 0; j < 12; j++) acc[i][j] += a[i] * w[j];
            }
        }
        #pragma unroll
        for (int j = 0; j < 12; j++) {
            int dd = tx + 16 * j;
            float bv = __ldg(&qkv_b[(dd >> 5) * 96 + (dd & 31)]);
            #pragma unroll
            for (int i = 0; i < 8; i++)
                Bs[(ty + 16 * i) * ASTR + dd] = acc[i][j] + bv;
        }
    }
    __syncthreads();

    // load kv into Ws (6144 floats) — q-GEMM is done with Ws now
    for (int idx = tid; idx < HEADS * HEADC * HEADC; idx += 256)
        Ws[idx] = g_kv[(size_t)bi * HEADS * HEADC * HEADC + idx];
    __syncthreads();

    // attn: A[p][h*32+e] += sum_d Bs[p][h*32+d] * kv[h][d][e]
    {
        int txa = tid & 7;    // cols e = txa*4 + j (j<4)
        int tya = tid >> 3;   // rows r = tya + 32*i (i<4)
        for (int h = 0; h < HEADS; h++) {
            float acc[4][4];
            #pragma unroll
            for (int i = 0; i < 4; i++)
                #pragma unroll
                for (int j = 0; j < 4; j++) acc[i][j] = 0.f;
            #pragma unroll 8
            for (int d = 0; d < 32; d++) {
                float q0 = Bs[(tya +  0) * ASTR + h * 32 + d];
                float q1 = Bs[(tya + 32) * ASTR + h * 32 + d];
                float q2 = Bs[(tya + 64) * ASTR + h * 32 + d];
                float q3 = Bs[(tya + 96) * ASTR + h * 32 + d];
                const float* kvrow = &Ws[(h * 32 + d) * 32 + txa * 4];
                #pragma unroll
                for (int j = 0; j < 4; j++) {
                    float kvv = kvrow[j];
                    acc[0][j] += q0 * kvv;
                    acc[1][j] += q1 * kvv;
                    acc[2][j] += q2 * kvv;
                    acc[3][j] += q3 * kvv;
                }
            }
            #pragma unroll
            for (int i = 0; i < 4; i++)
                #pragma unroll
                for (int j = 0; j < 4; j++)
                    A[(tya + 32 * i) * ASTR + h * 32 + txa * 4 + j] += acc[i][j];
        }
    }
    __syncthreads();

    // GEMM1: h = gelu(A @ o1w^T + o1b) -> Bs
    {
        float acc[8][12];
        #pragma unroll
        for (int i = 0; i < 8; i++)
            #pragma unroll
            for (int j = 0; j < 12; j++) acc[i][j] = 0.f;

        for (int k0 = 0; k0 < CC; k0 += 16) {
            __syncthreads();
            for (int idx = tid; idx < 192 * 4; idx += 256) {
                int d = idx >> 2, kk = (idx & 3) << 2;
                float4 v = *reinterpret_cast<const float4*>(&o1w[(size_t)d * CC + k0 + kk]);
                Ws[d * 17 + kk + 0] = v.x;
                Ws[d * 17 + kk + 1] = v.y;
                Ws[d * 17 + kk + 2] = v.z;
                Ws[d * 17 + kk + 3] = v.w;
            }
            __syncthreads();
            #pragma unroll
            for (int k = 0; k < 16; k++) {
                float a[8], w[12];
                #pragma unroll
                for (int i = 0; i < 8; i++) a[i] = A[(ty + 16 * i) * ASTR + k0 + k];
                #pragma unroll
                for (int j = 0; j < 12; j++) w[j] = Ws[(tx + 16 * j) * 17 + k];
                #pragma unroll
                for (int i = 0; i < 8; i++)
                    #pragma unroll
                    for (int j = 0; j < 12; j++) acc[i][j] += a[i] * w[j];
            }
        }
        __syncthreads();
        #pragma unroll
        for (int j = 0; j < 12; j++) {
            int d = tx + 16 * j;
            float bb = __ldg(&o1b[d]);
            #pragma unroll
            for (int i = 0; i < 8; i++) {
                float t = acc[i][j] + bb;
                float g = 0.5f * t * (1.f + erff(t * 0.70710678118654752f));
                Bs[(ty + 16 * i) * ASTR + d] = g;
            }
        }
    }

    // GEMM2: out = Bs @ o2w^T + o2b + x
    {
        float acc[8][12];
        #pragma unroll
        for (int i = 0; i < 8; i++)
            #pragma unroll
            for (int j = 0; j < 12; j++) acc[i][j] = 0.f;

        for (int k0 = 0; k0 < CC; k0 += 16) {
            __syncthreads();
            for (int idx = tid; idx < 192 * 4; idx += 256) {
                int d = idx >> 2, kk = (idx & 3) << 2;
                float4 v = *reinterpret_cast<const float4*>(&o2w[(size_t)d * CC + k0 + kk]);
                Ws[d * 17 + kk + 0] = v.x;
                Ws[d * 17 + kk + 1] = v.y;
                Ws[d * 17 + kk + 2] = v.z;
                Ws[d * 17 + kk + 3] = v.w;
            }
            __syncthreads();
            #pragma unroll
            for (int k = 0; k < 16; k++) {
                float a[8], w[12];
                #pragma unroll
                for (int i = 0; i < 8; i++) a[i] = Bs[(ty + 16 * i) * ASTR + k0 + k];
                #pragma unroll
                for (int j = 0; j < 12; j++) w[j] = Ws[(tx + 16 * j) * 17 + k];
                #pragma unroll
                for (int i = 0; i < 8; i++)
                    #pragma unroll
                    for (int j = 0; j < 12; j++) acc[i][j] += a[i] * w[j];
            }
        }
        #pragma unroll
        for (int j = 0; j < 12; j++) {
            int d = tx + 16 * j;
            float b2 = __ldg(&o2b[d]);
            #pragma unroll
            for (int i = 0; i < 8; i++) {
                int r = ty + 16 * i;
                out[(size_t)(m0 + r) * CC + d] =
                    acc[i][j] + b2 + __ldg(&x[(size_t)(m0 + r) * CC + d]);
            }
        }
    }
}

// ---------------------------------------------------------------------------

extern "C" void kernel_launch(void* const* d_in, const int* in_sizes, int n_in,
                              void* d_out, int out_size)
{
    const float* x     = (const float*)d_in[0];
    const float* qkv_w = (const float*)d_in[1];
    const float* qkv_b = (const float*)d_in[2];
    const float* o1w   = (const float*)d_in[3];
    const float* o1b   = (const float*)d_in[4];
    const float* o2w   = (const float*)d_in[5];
    const float* o2b   = (const float*)d_in[6];
    const float* klw   = (const float*)d_in[7];
    const float* klb   = (const float*)d_in[8];
    const float* vlw   = (const float*)d_in[9];
    const float* vlb   = (const float*)d_in[10];
    float* out = (float*)d_out;

    const int smem1 = (16 * 129 + 64 * 17 + 128 * 65) * 4;          // 45,888 B
    const int smem2 = (2 * 128 * ASTR + HEADS * HEADC * HEADC) * 4; // 225,280 B
    cudaFuncSetAttribute(k1_kv, cudaFuncAttributeMaxDynamicSharedMemorySize, smem1);
    cudaFuncSetAttribute(k2_attn_mlp, cudaFuncAttributeMaxDynamicSharedMemorySize, smem2);

    zero_kv_kernel<<<(BB * HEADS * HEADC * HEADC + 255) / 256, 256>>>();

    dim3 g1(MTOT / TM, HEADS);
    k1_kv<<<g1, 256, smem1>>>(x, qkv_w, qkv_b, klw, klb, vlw, vlb);

    k2_attn_mlp<<<MTOT / TM, 256, smem2>>>(x, qkv_w, qkv_b, o1w, o1b, o2w, o2b, out);
}

// round 7
// speedup vs baseline: 2.2884x; 2.2884x over previous
#include <cuda_runtime.h>
#include <math.h>

#define BB 4
#define NN 65536
#define CC 192
#define HEADS 6
#define HEADC 32
#define MTOT (BB*NN)
#define TM 128
#define EPS 1e-5f
#define ASTR 196
#define WSTR 20
#define KVSTR 36

// only device-global scratch: tiny kv accumulator
__device__ float g_kv[BB * HEADS * HEADC * HEADC];

__global__ void zero_kv_kernel() {
    int i = blockIdx.x * blockDim.x + threadIdx.x;
    if (i < BB * HEADS * HEADC * HEADC) g_kv[i] = 0.f;
}

__device__ __forceinline__ unsigned f2tf(float f) {
    unsigned u;
    asm("cvt.rna.tf32.f32 %0, %1;" : "=r"(u) : "f"(f));
    return u;
}

__device__ __forceinline__ void mma8(float* c,
    unsigned a0, unsigned a1, unsigned a2, unsigned a3,
    unsigned b0, unsigned b1)
{
    asm volatile(
        "mma.sync.aligned.m16n8k8.row.col.f32.tf32.tf32.f32 "
        "{%0,%1,%2,%3}, {%4,%5,%6,%7}, {%8,%9}, {%0,%1,%2,%3};"
        : "+f"(c[0]), "+f"(c[1]), "+f"(c[2]), "+f"(c[3])
        : "r"(a0), "r"(a1), "r"(a2), "r"(a3), "r"(b0), "r"(b1));
}

// ---------------------------------------------------------------------------
// Kernel 1: k,v projection (one head per block) via TF32 mma, LN(k), LN(v),
// kv outer-product accumulation.
// grid: (HEADS, MTOT/TM)  [head fastest -> L2 reuse of x tile], block: 256
// smem: As[2][128][20] + Wk[2][64][20] + Res[128][68] = 65,536 B
// ---------------------------------------------------------------------------
__global__ __launch_bounds__(256) void k1_kv(
    const float* __restrict__ x, const float* __restrict__ qkv_w,
    const float* __restrict__ qkv_b,
    const float* __restrict__ klw, const float* __restrict__ klb,
    const float* __restrict__ vlw, const float* __restrict__ vlb)
{
    extern __shared__ float sm[];
    float* As  = sm;                               // 2 * 128*20 = 5120
    float* Wk  = sm + 2 * 128 * WSTR;              // 2 * 64*20  = 2560
    float* Res = sm + 2 * 128 * WSTR + 2 * 64 * WSTR;  // 128*68 = 8704

    const int tid  = threadIdx.x;
    const int head = blockIdx.x;
    const int m0   = blockIdx.y * TM;
    const int wbase = head * 96 + 32;              // k rows, then v rows

    const int warp = tid >> 5, lane = tid & 31;
    const int gid = lane >> 2, tig = lane & 3;
    const int m0w = (warp >> 1) * 32, n0w = (warp & 1) * 32;

    float4 xr[2], wreg;

    float acc[2][4][4];
    #pragma unroll
    for (int i = 0; i < 2; i++)
        #pragma unroll
        for (int j = 0; j < 4; j++)
            #pragma unroll
            for (int e = 0; e < 4; e++) acc[i][j][e] = 0.f;

    // prefetch chunk 0
    {
        #pragma unroll
        for (int t = 0; t < 2; t++) {
            int idx = tid + t * 256, p = idx >> 2, kk = (idx & 3) << 2;
            xr[t] = *(const float4*)&x[(size_t)(m0 + p) * CC + kk];
        }
        int d = tid >> 2, kk = (tid & 3) << 2;
        wreg = *(const float4*)&qkv_w[(size_t)(wbase + d) * CC + kk];
    }

    #pragma unroll 1
    for (int c = 0; c < 12; c++) {
        // STS chunk c
        {
            #pragma unroll
            for (int t = 0; t < 2; t++) {
                int idx = tid + t * 256, p = idx >> 2, kk = (idx & 3) << 2;
                *(float4*)&As[(c & 1) * 128 * WSTR + p * WSTR + kk] = xr[t];
            }
            int d = tid >> 2, kk = (tid & 3) << 2;
            *(float4*)&Wk[(c & 1) * 64 * WSTR + d * WSTR + kk] = wreg;
        }
        // LDG chunk c+1
        if (c < 11) {
            int k0 = (c + 1) * 16;
            #pragma unroll
            for (int t = 0; t < 2; t++) {
                int idx = tid + t * 256, p = idx >> 2, kk = (idx & 3) << 2;
                xr[t] = *(const float4*)&x[(size_t)(m0 + p) * CC + k0 + kk];
            }
            int d = tid >> 2, kk = (tid & 3) << 2;
            wreg = *(const float4*)&qkv_w[(size_t)(wbase + d) * CC + k0 + kk];
        }
        __syncthreads();
        const float* Ab = &As[(c & 1) * 128 * WSTR];
        const float* Wb = &Wk[(c & 1) * 64 * WSTR];
        #pragma unroll
        for (int s = 0; s < 2; s++) {
            int kk = 8 * s + tig;
            unsigned a[2][4];
            #pragma unroll
            for (int i = 0; i < 2; i++) {
                const float* ap = &Ab[(m0w + 16 * i + gid) * WSTR + kk];
                a[i][0] = f2tf(ap[0]);
                a[i][1] = f2tf(ap[8 * WSTR]);
                a[i][2] = f2tf(ap[4]);
                a[i][3] = f2tf(ap[8 * WSTR + 4]);
            }
            #pragma unroll
            for (int j = 0; j < 4; j++) {
                const float* bp = &Wb[(n0w + 8 * j + gid) * WSTR + kk];
                unsigned b0 = f2tf(bp[0]), b1 = f2tf(bp[4]);
                mma8(acc[0][j], a[0][0], a[0][1], a[0][2], a[0][3], b0, b1);
                mma8(acc[1][j], a[1][0], a[1][1], a[1][2], a[1][3], b0, b1);
            }
        }
    }

    // epilogue: +bias -> Res
    #pragma unroll
    for (int j = 0; j < 4; j++) {
        int c0 = n0w + 8 * j + 2 * tig;
        float b0 = __ldg(&qkv_b[wbase + c0]);
        float b1 = __ldg(&qkv_b[wbase + c0 + 1]);
        #pragma unroll
        for (int i = 0; i < 2; i++) {
            int r = m0w + 16 * i + gid;
            Res[r * 68 + c0]           = acc[i][j][0] + b0;
            Res[r * 68 + c0 + 1]       = acc[i][j][1] + b1;
            Res[(r + 8) * 68 + c0]     = acc[i][j][2] + b0;
            Res[(r + 8) * 68 + c0 + 1] = acc[i][j][3] + b1;
        }
    }
    __syncthreads();

    // LN on k (cols 0..31) and v (cols 32..63); ddof=1, denom = std + eps
    {
        int p = tid & 127;
        int which = tid >> 7;               // 0 -> k, 1 -> v
        int base = which ? 32 : 0;
        const float* lw = which ? vlw : klw;
        const float* lb = which ? vlb : klb;
        float s = 0.f, s2 = 0.f;
        #pragma unroll
        for (int c = 0; c < 32; c++) {
            float v = Res[p * 68 + base + c];
            s += v; s2 += v * v;
        }
        float mean = s * (1.f / 32.f);
        float var = (s2 - s * mean) * (1.f / 31.f);
        var = fmaxf(var, 0.f);
        float inv = 1.f / (sqrtf(var) + EPS);
        #pragma unroll
        for (int c = 0; c < 32; c++) {
            float v = Res[p * 68 + base + c];
            Res[p * 68 + base + c] =
                __ldg(&lw[head * 32 + c]) * ((v - mean) * inv) + __ldg(&lb[head * 32 + c]);
        }
    }
    __syncthreads();

    // kv outer product (fp32 exact): kv[d][e] += sum_p k[p][d]*v[p][e] / N
    {
        int d  = tid >> 3;
        int e0 = (tid & 7) << 2;
        float a0 = 0.f, a1 = 0.f, a2 = 0.f, a3 = 0.f;
        for (int p = 0; p < TM; p++) {
            float kd = Res[p * 68 + d];
            a0 += kd * Res[p * 68 + 32 + e0 + 0];
            a1 += kd * Res[p * 68 + 32 + e0 + 1];
            a2 += kd * Res[p * 68 + 32 + e0 + 2];
            a3 += kd * Res[p * 68 + 32 + e0 + 3];
        }
        int bi = m0 / NN;
        float* dst = &g_kv[(((size_t)bi * HEADS + head) * HEADC + d) * HEADC + e0];
        const float sc = 1.f / (float)NN;
        atomicAdd(dst + 0, a0 * sc);
        atomicAdd(dst + 1, a1 * sc);
        atomicAdd(dst + 2, a2 * sc);
        atomicAdd(dst + 3, a3 * sc);
    }
}

// ---------------------------------------------------------------------------
// Kernel 2: q proj -> attn (q@kv) + residual -> GELU MLP, all TF32 mma.
// grid: MTOT/TM, block: 256
// smem: A[128][196] + Bs[128][196] + Wc[2*192*20] = 231,424 B
// ---------------------------------------------------------------------------
__global__ __launch_bounds__(256) void k2_attn_mlp(
    const float* __restrict__ x,
    const float* __restrict__ qkv_w, const float* __restrict__ qkv_b,
    const float* __restrict__ o1w, const float* __restrict__ o1b,
    const float* __restrict__ o2w, const float* __restrict__ o2b,
    float* __restrict__ out)
{
    extern __shared__ float sm[];
    float* A  = sm;                       // 128*196
    float* Bs = sm + 128 * ASTR;          // 128*196
    float* Wc = sm + 2 * 128 * ASTR;      // 2*192*20 = 7680 fl; doubles as kvT[192][36]

    const int tid = threadIdx.x;
    const int m0  = blockIdx.x * TM;
    const int bi  = m0 / NN;
    const int warp = tid >> 5, lane = tid & 31;
    const int gid = lane >> 2, tig = lane & 3;
    const int m0w = (warp >> 1) * 32, n0w = (warp & 1) * 96;

    // stage 0: x -> A
    for (int idx = tid; idx < TM * CC / 4; idx += 256) {
        int p = idx / 48, c4 = (idx % 48) * 4;
        *(float4*)&A[p * ASTR + c4] = *(const float4*)&x[(size_t)(m0 + p) * CC + c4];
    }
    __syncthreads();

    float4 wr[3];
    float acc[2][12][4];

    auto zeroacc = [&]() {
        #pragma unroll
        for (int i = 0; i < 2; i++)
            #pragma unroll
            for (int j = 0; j < 12; j++)
                #pragma unroll
                for (int e = 0; e < 4; e++) acc[i][j][e] = 0.f;
    };
    auto ldgW = [&](const float* W, int k0) {
        #pragma unroll
        for (int t = 0; t < 3; t++) {
            int idx = tid + t * 256, d = idx >> 2, kk = (idx & 3) << 2;
            wr[t] = *(const float4*)&W[(size_t)d * CC + k0 + kk];
        }
    };
    auto ldgWq = [&](int k0) {
        #pragma unroll
        for (int t = 0; t < 3; t++) {
            int idx = tid + t * 256, d = idx >> 2, kk = (idx & 3) << 2;
            int grow = (d >> 5) * 96 + (d & 31);   // q rows of head d>>5
            wr[t] = *(const float4*)&qkv_w[(size_t)grow * CC + k0 + kk];
        }
    };
    auto stsW = [&](int buf) {
        #pragma unroll
        for (int t = 0; t < 3; t++) {
            int idx = tid + t * 256, d = idx >> 2, kk = (idx & 3) << 2;
            *(float4*)&Wc[buf * (192 * WSTR) + d * WSTR + kk] = wr[t];
        }
    };
    auto mmachunk = [&](const float* Asrc, int k0, int buf) {
        const float* Wb = &Wc[buf * (192 * WSTR)];
        #pragma unroll
        for (int s = 0; s < 2; s++) {
            int kk = k0 + 8 * s + tig;
            unsigned a[2][4];
            #pragma unroll
            for (int i = 0; i < 2; i++) {
                const float* ap = &Asrc[(m0w + 16 * i + gid) * ASTR + kk];
                a[i][0] = f2tf(ap[0]);
                a[i][1] = f2tf(ap[8 * ASTR]);
                a[i][2] = f2tf(ap[4]);
                a[i][3] = f2tf(ap[8 * ASTR + 4]);
            }
            #pragma unroll
            for (int j = 0; j < 12; j++) {
                const float* bp = &Wb[(n0w + 8 * j + gid) * WSTR + 8 * s + tig];
                unsigned b0 = f2tf(bp[0]), b1 = f2tf(bp[4]);
                mma8(acc[0][j], a[0][0], a[0][1], a[0][2], a[0][3], b0, b1);
                mma8(acc[1][j], a[1][0], a[1][1], a[1][2], a[1][3], b0, b1);
            }
        }
    };

    // ---------------- q projection: Bs = A @ Wq^T + bq ----------------
    zeroacc();
    ldgWq(0);
    #pragma unroll 1
    for (int c = 0; c < 12; c++) {
        stsW(c & 1);
        if (c < 11) ldgWq((c + 1) * 16);
        __syncthreads();
        mmachunk(A, c * 16, c & 1);
    }
    #pragma unroll
    for (int j = 0; j < 12; j++) {
        int c0 = n0w + 8 * j + 2 * tig;
        float b0 = __ldg(&qkv_b[(c0 >> 5) * 96 + (c0 & 31)]);
        float b1 = __ldg(&qkv_b[(c0 >> 5) * 96 + (c0 & 31) + 1]);
        #pragma unroll
        for (int i = 0; i < 2; i++) {
            int r = m0w + 16 * i + gid;
            Bs[r * ASTR + c0]           = acc[i][j][0] + b0;
            Bs[r * ASTR + c0 + 1]       = acc[i][j][1] + b1;
            Bs[(r + 8) * ASTR + c0]     = acc[i][j][2] + b0;
            Bs[(r + 8) * ASTR + c0 + 1] = acc[i][j][3] + b1;
        }
    }
    __syncthreads();   // all warps done with Wc before kvT staging

    // ---------------- stage kv transposed: kvT[(h*32+e)][d] ----------------
    for (int idx = tid; idx < HEADS * HEADC * HEADC; idx += 256) {
        int hd = idx >> 5, e = idx & 31;
        int h = hd >> 5, d = hd & 31;
        Wc[(h * 32 + e) * KVSTR + d] = g_kv[(size_t)bi * HEADS * HEADC * HEADC + idx];
    }
    __syncthreads();

    // ---------------- attn: A = x + q @ kv (block-diag per head) ----------------
    {
        float aacc[2][12][4];
        #pragma unroll
        for (int j = 0; j < 12; j++) {
            int c0 = n0w + 8 * j + 2 * tig;
            #pragma unroll
            for (int i = 0; i < 2; i++) {
                int r = m0w + 16 * i + gid;
                aacc[i][j][0] = A[r * ASTR + c0];
                aacc[i][j][1] = A[r * ASTR + c0 + 1];
                aacc[i][j][2] = A[(r + 8) * ASTR + c0];
                aacc[i][j][3] = A[(r + 8) * ASTR + c0 + 1];
            }
        }
        int h0 = n0w >> 5;   // first of this warp's 3 heads
        #pragma unroll
        for (int s = 0; s < 4; s++) {
            unsigned qa[3][2][4];
            #pragma unroll
            for (int hh = 0; hh < 3; hh++) {
                int cb = (h0 + hh) * 32 + 8 * s + tig;
                #pragma unroll
                for (int i = 0; i < 2; i++) {
                    const float* qp = &Bs[(m0w + 16 * i + gid) * ASTR + cb];
                    qa[hh][i][0] = f2tf(qp[0]);
                    qa[hh][i][1] = f2tf(qp[8 * ASTR]);
                    qa[hh][i][2] = f2tf(qp[4]);
                    qa[hh][i][3] = f2tf(qp[8 * ASTR + 4]);
                }
            }
            #pragma unroll
            for (int j = 0; j < 12; j++) {
                int hh = j >> 2;
                const float* bp = &Wc[(n0w + 8 * j + gid) * KVSTR + 8 * s + tig];
                unsigned b0 = f2tf(bp[0]), b1 = f2tf(bp[4]);
                mma8(aacc[0][j], qa[hh][0][0], qa[hh][0][1], qa[hh][0][2], qa[hh][0][3], b0, b1);
                mma8(aacc[1][j], qa[hh][1][0], qa[hh][1][1], qa[hh][1][2], qa[hh][1][3], b0, b1);
            }
        }
        #pragma unroll
        for (int j = 0; j < 12; j++) {
            int c0 = n0w + 8 * j + 2 * tig;
            #pragma unroll
            for (int i = 0; i < 2; i++) {
                int r = m0w + 16 * i + gid;
                A[r * ASTR + c0]           = aacc[i][j][0];
                A[r * ASTR + c0 + 1]       = aacc[i][j][1];
                A[(r + 8) * ASTR + c0]     = aacc[i][j][2];
                A[(r + 8) * ASTR + c0 + 1] = aacc[i][j][3];
            }
        }
    }
    __syncthreads();   // ret visible to all; kvT free

    // ---------------- GEMM1: Bs = gelu(A @ o1w^T + o1b) ----------------
    zeroacc();
    ldgW(o1w, 0);
    #pragma unroll 1
    for (int c = 0; c < 12; c++) {
        stsW(c & 1);
        if (c < 11) ldgW(o1w, (c + 1) * 16);
        __syncthreads();
        mmachunk(A, c * 16, c & 1);
    }
    #pragma unroll
    for (int j = 0; j < 12; j++) {
        int c0 = n0w + 8 * j + 2 * tig;
        float b0 = __ldg(&o1b[c0]);
        float b1 = __ldg(&o1b[c0 + 1]);
        #pragma unroll
        for (int i = 0; i < 2; i++) {
            int r = m0w + 16 * i + gid;
            float t0 = acc[i][j][0] + b0;
            float t1 = acc[i][j][1] + b1;
            float t2 = acc[i][j][2] + b0;
            float t3 = acc[i][j][3] + b1;
            Bs[r * ASTR + c0]           = 0.5f * t0 * (1.f + erff(t0 * 0.70710678118654752f));
            Bs[r * ASTR + c0 + 1]       = 0.5f * t1 * (1.f + erff(t1 * 0.70710678118654752f));
            Bs[(r + 8) * ASTR + c0]     = 0.5f * t2 * (1.f + erff(t2 * 0.70710678118654752f));
            Bs[(r + 8) * ASTR + c0 + 1] = 0.5f * t3 * (1.f + erff(t3 * 0.70710678118654752f));
        }
    }

    // ---------------- GEMM2: out = Bs @ o2w^T + o2b + x ----------------
    zeroacc();
    ldgW(o2w, 0);
    #pragma unroll 1
    for (int c = 0; c < 12; c++) {
        stsW(c & 1);
        if (c < 11) ldgW(o2w, (c + 1) * 16);
        __syncthreads();
        mmachunk(Bs, c * 16, c & 1);
    }
    // write raw acc -> A, then coalesced epilogue store
    #pragma unroll
    for (int j = 0; j < 12; j++) {
        int c0 = n0w + 8 * j + 2 * tig;
        #pragma unroll
        for (int i = 0; i < 2; i++) {
            int r = m0w + 16 * i + gid;
            A[r * ASTR + c0]           = acc[i][j][0];
            A[r * ASTR + c0 + 1]       = acc[i][j][1];
            A[(r + 8) * ASTR + c0]     = acc[i][j][2];
            A[(r + 8) * ASTR + c0 + 1] = acc[i][j][3];
        }
    }
    __syncthreads();
    for (int idx = tid; idx < TM * CC / 4; idx += 256) {
        int p = idx / 48, c4 = (idx % 48) * 4;
        float4 av = *(float4*)&A[p * ASTR + c4];
        float4 bv = *(const float4*)&o2b[c4];
        float4 xv = *(const float4*)&x[(size_t)(m0 + p) * CC + c4];
        av.x += bv.x + xv.x;
        av.y += bv.y + xv.y;
        av.z += bv.z + xv.z;
        av.w += bv.w + xv.w;
        *(float4*)&out[(size_t)(m0 + p) * CC + c4] = av;
    }
}

// ---------------------------------------------------------------------------

extern "C" void kernel_launch(void* const* d_in, const int* in_sizes, int n_in,
                              void* d_out, int out_size)
{
    const float* x     = (const float*)d_in[0];
    const float* qkv_w = (const float*)d_in[1];
    const float* qkv_b = (const float*)d_in[2];
    const float* o1w   = (const float*)d_in[3];
    const float* o1b   = (const float*)d_in[4];
    const float* o2w   = (const float*)d_in[5];
    const float* o2b   = (const float*)d_in[6];
    const float* klw   = (const float*)d_in[7];
    const float* klb   = (const float*)d_in[8];
    const float* vlw   = (const float*)d_in[9];
    const float* vlb   = (const float*)d_in[10];
    float* out = (float*)d_out;

    const int smem1 = (2 * 128 * WSTR + 2 * 64 * WSTR + 128 * 68) * 4;   // 65,536 B
    const int smem2 = (2 * 128 * ASTR + 2 * 192 * WSTR) * 4;             // 231,424 B
    cudaFuncSetAttribute(k1_kv, cudaFuncAttributeMaxDynamicSharedMemorySize, smem1);
    cudaFuncSetAttribute(k2_attn_mlp, cudaFuncAttributeMaxDynamicSharedMemorySize, smem2);

    zero_kv_kernel<<<(BB * HEADS * HEADC * HEADC + 255) / 256, 256>>>();

    dim3 g1(HEADS, MTOT / TM);
    k1_kv<<<g1, 256, smem1>>>(x, qkv_w, qkv_b, klw, klb, vlw, vlb);

    k2_attn_mlp<<<MTOT / TM, 256, smem2>>>(x, qkv_w, qkv_b, o1w, o1b, o2w, o2b, out);
}